// round 6
// baseline (speedup 1.0000x reference)
#include <cuda_runtime.h>
#include <cstdint>
#include <cstddef>

// Problem constants: B=4, S=4096, D=512, chunk C=256
#define ROWS_TOTAL 16384
#define DIMD 512
#define CCHUNK 256
#define NCHUNKS 64
#define CHUNKS_PER_BATCH 16

#define NE  ((size_t)ROWS_TOTAL * DIMD)          // 8,388,608
#define STN ((size_t)NCHUNKS * DIMD * DIMD)      // 16,777,216
#define SCN ((size_t)NCHUNKS * CCHUNK * CCHUNK)  // 4,194,304

// ---------------------------------------------------------------------------
// Scratch (static device globals; no allocation)
// ---------------------------------------------------------------------------
__device__ __align__(16) int8_t g_x1[NE], g_x2[NE];
__device__ float g_sx[ROWS_TOTAL];
__device__ __align__(16) int8_t g_w1[(size_t)2048 * 512], g_w2[(size_t)2048 * 512];
__device__ float g_sw[2048];
__device__ __align__(16) float  g_qkv[(size_t)ROWS_TOTAL * 1536];   // f32 q|k|v
__device__ __align__(16) int8_t g_q1[NE], g_q2[NE], g_k1[NE], g_k2[NE];
__device__ float g_sq[ROWS_TOTAL], g_sk[ROWS_TOTAL];
__device__ __align__(16) int8_t g_kt1[NE], g_kt2[NE], g_vt1[NE], g_vt2[NE];
__device__ float g_skt[NCHUNKS * DIMD], g_svt[NCHUNKS * DIMD];
__device__ __align__(16) float  g_st[STN];                           // per-chunk state f32
__device__ __align__(16) int8_t g_p1[STN], g_p2[STN];
__device__ float g_sp[NCHUNKS * DIMD];
__device__ __align__(16) float  g_scf[SCN];
__device__ __align__(16) int8_t g_s1[SCN], g_s2[SCN];
__device__ float g_ss[ROWS_TOTAL];
__device__ __align__(16) float  g_y[NE];
__device__ __align__(16) int8_t g_y1[NE], g_y2[NE];
__device__ float g_sy[ROWS_TOTAL];

// ---------------------------------------------------------------------------
// helpers
// ---------------------------------------------------------------------------
__device__ __forceinline__ uint32_t smem_u32(const void* p) {
    uint32_t a;
    asm("{ .reg .u64 t; cvta.to.shared.u64 t, %1; cvt.u32.u64 %0, t; }" : "=r"(a) : "l"(p));
    return a;
}
__device__ __forceinline__ void cp16(uint32_t dst, const void* src) {
    asm volatile("cp.async.cg.shared.global [%0], [%1], 16;" :: "r"(dst), "l"(src));
}
#define CP_COMMIT() asm volatile("cp.async.commit_group;" ::: "memory")
template <int N> __device__ __forceinline__ void cp_wait() {
    asm volatile("cp.async.wait_group %0;" :: "n"(N) : "memory");
}
__device__ __forceinline__ void ldm4(uint32_t* r, uint32_t addr) {
    asm volatile("ldmatrix.sync.aligned.m8n8.x4.shared.b16 {%0,%1,%2,%3}, [%4];"
                 : "=r"(r[0]), "=r"(r[1]), "=r"(r[2]), "=r"(r[3]) : "r"(addr));
}
__device__ __forceinline__ void imma(int* d, const uint32_t* a, uint32_t b0, uint32_t b1) {
    asm volatile("mma.sync.aligned.m16n8k32.row.col.s32.s8.s8.s32 "
                 "{%0,%1,%2,%3},{%4,%5,%6,%7},{%8,%9},{%0,%1,%2,%3};"
                 : "+r"(d[0]), "+r"(d[1]), "+r"(d[2]), "+r"(d[3])
                 : "r"(a[0]), "r"(a[1]), "r"(a[2]), "r"(a[3]), "r"(b0), "r"(b1));
}
// quantize one float given inv = 127/rowmax
__device__ __forceinline__ void q2(float v, float inv, int& o1, int& o2) {
    float q = v * inv;
    float r1 = rintf(q);
    float r2 = rintf((q - r1) * 256.0f);
    r1 = fminf(fmaxf(r1, -127.0f), 127.0f);
    r2 = fminf(fmaxf(r2, -127.0f), 127.0f);
    o1 = (int)r1; o2 = (int)r2;
}
__device__ __forceinline__ uint32_t pack4(int a, int b, int c, int d) {
    return (uint32_t)(a & 0xFF) | ((uint32_t)(b & 0xFF) << 8) |
           ((uint32_t)(c & 0xFF) << 16) | ((uint32_t)(d & 0xFF) << 24);
}

// ---------------------------------------------------------------------------
// int8 GEMM: CTA 128x128, 8 warps (2m x 4n), warp tile 64x32, k-chunk 64.
// C[m,n] = sa[m]*sb[n]*(P11 + Pmid/256), P11=A1B1, Pmid=A1B2+A2B1 (s32 exact)
// MODE 0: plain f32 out; MODE 2: + causal mask; MODE 3: + aux add (in-place ok)
// ---------------------------------------------------------------------------
#define GSMEM 65536

template <int MODE>
__global__ __launch_bounds__(256, 1)
void gemm_i8(const int8_t* __restrict__ A1, const int8_t* __restrict__ A2,
             long sAz, int lda, const float* __restrict__ sa, int saz,
             const int8_t* __restrict__ B1, const int8_t* __restrict__ B2,
             long sBz, int ldb, const float* __restrict__ sb, int sbz,
             float* __restrict__ C, long sCz, int ldc,
             const float* __restrict__ aux, int K)
{
    extern __shared__ __align__(128) char dsm[];
    const uint32_t sm = smem_u32(dsm);
    const int tid = threadIdx.x, lane = tid & 31, wid = tid >> 5;
    const int wm = wid & 1, wn = wid >> 1;
    const long z = blockIdx.z;
    const int bm = blockIdx.y * 128, bn = blockIdx.x * 128;

    const int8_t* A1p = A1 + z * sAz + (long)bm * lda;
    const int8_t* A2p = A2 + z * sAz + (long)bm * lda;
    const int8_t* B1p = B1 + z * sBz + (long)bn * ldb;
    const int8_t* B2p = B2 + z * sBz + (long)bn * ldb;

    int acc1[4][4][4], accm[4][4][4];
#pragma unroll
    for (int i = 0; i < 4; i++)
#pragma unroll
        for (int j = 0; j < 4; j++)
#pragma unroll
            for (int q = 0; q < 4; q++) { acc1[i][j][q] = 0; accm[i][j][q] = 0; }

    // SMEM buffer: A 128 rows x 128B (8 chunks of 16B: ch = slice*4 + kseg),
    // B likewise at +16KB. swizzle: (ch ^ (row&7))<<4
    auto load = [&](int c, int buf) {
        const int k0 = c * 64;
        const uint32_t sbuf = sm + buf * 32768;
#pragma unroll
        for (int i = 0; i < 4; i++) {
            int e = tid + 256 * i;
            int row = e >> 3, ch = e & 7;
            const int8_t* src = ((ch >> 2) ? A2p : A1p) + (long)row * lda + k0 + (ch & 3) * 16;
            cp16(sbuf + row * 128 + ((ch ^ (row & 7)) << 4), src);
        }
#pragma unroll
        for (int i = 0; i < 4; i++) {
            int e = tid + 256 * i;
            int row = e >> 3, ch = e & 7;
            const int8_t* src = ((ch >> 2) ? B2p : B1p) + (long)row * ldb + k0 + (ch & 3) * 16;
            cp16(sbuf + 16384 + row * 128 + ((ch ^ (row & 7)) << 4), src);
        }
    };

    auto compute = [&](int buf) {
        const uint32_t ba = sm + buf * 32768;
        const uint32_t bb = ba + 16384;
#pragma unroll
        for (int ks = 0; ks < 2; ks++) {
            uint32_t a1f[4][4], a2f[4][4];
#pragma unroll
            for (int mf = 0; mf < 4; mf++) {
                int row = wm * 64 + mf * 16 + (lane & 7) + ((lane >> 3) & 1) * 8;
                int c1 = ks * 2 + (lane >> 4);
                ldm4(a1f[mf], ba + row * 128 + ((c1 ^ (row & 7)) << 4));
                ldm4(a2f[mf], ba + row * 128 + (((c1 + 4) ^ (row & 7)) << 4));
            }
#pragma unroll
            for (int p = 0; p < 2; p++) {
                uint32_t b1f[4], b2f[4];
                int row = wn * 32 + p * 16 + (lane & 7) + (lane >> 4) * 8;
                int c1 = ks * 2 + ((lane >> 3) & 1);
                ldm4(b1f, bb + row * 128 + ((c1 ^ (row & 7)) << 4));
                ldm4(b2f, bb + row * 128 + (((c1 + 4) ^ (row & 7)) << 4));
#pragma unroll
                for (int half = 0; half < 2; half++) {
                    int nf = p * 2 + half;
                    uint32_t bh0 = b1f[2 * half], bh1 = b1f[2 * half + 1];
                    uint32_t bl0 = b2f[2 * half], bl1 = b2f[2 * half + 1];
#pragma unroll
                    for (int mf = 0; mf < 4; mf++) {
                        imma(acc1[mf][nf], a1f[mf], bh0, bh1);
                        imma(accm[mf][nf], a1f[mf], bl0, bl1);
                        imma(accm[mf][nf], a2f[mf], bh0, bh1);
                    }
                }
            }
        }
    };

    const int nch = K >> 6;
    load(0, 0); CP_COMMIT();
    for (int c = 0; c < nch; c++) {
        if (c + 1 < nch) { load(c + 1, (c + 1) & 1); CP_COMMIT(); cp_wait<1>(); }
        else             { cp_wait<0>(); }
        __syncthreads();
        compute(c & 1);
        __syncthreads();
    }

    const float i256 = 0.00390625f;
#pragma unroll
    for (int mf = 0; mf < 4; mf++) {
        int rl = wm * 64 + mf * 16 + (lane >> 2);
        float sa0 = sa[(long)z * saz + bm + rl];
        float sa1 = sa[(long)z * saz + bm + rl + 8];
#pragma unroll
        for (int nf = 0; nf < 4; nf++) {
            int cl = wn * 32 + nf * 8 + (lane & 3) * 2;
            float sb0 = sb[(long)z * sbz + bn + cl];
            float sb1 = sb[(long)z * sbz + bn + cl + 1];
            int* p1 = acc1[mf][nf]; int* pm = accm[mf][nf];
            float v0 = sa0 * sb0 * ((float)p1[0] + (float)pm[0] * i256);
            float v1 = sa0 * sb1 * ((float)p1[1] + (float)pm[1] * i256);
            float v2 = sa1 * sb0 * ((float)p1[2] + (float)pm[2] * i256);
            float v3 = sa1 * sb1 * ((float)p1[3] + (float)pm[3] * i256);
            if (MODE == 2) {
                if (bn + cl     > bm + rl)     v0 = 0.0f;
                if (bn + cl + 1 > bm + rl)     v1 = 0.0f;
                if (bn + cl     > bm + rl + 8) v2 = 0.0f;
                if (bn + cl + 1 > bm + rl + 8) v3 = 0.0f;
            }
            long i0 = z * sCz + (long)(bm + rl) * ldc + bn + cl;
            long i1 = i0 + 8L * ldc;
            if (MODE == 3) { v0 += aux[i0]; v1 += aux[i0 + 1]; v2 += aux[i1]; v3 += aux[i1 + 1]; }
            *(float2*)(C + i0) = make_float2(v0, v1);
            *(float2*)(C + i1) = make_float2(v2, v3);
        }
    }
}

// ---------------------------------------------------------------------------
// row-wise quantization: 1 warp per row, cols in {256, 512} (multiple of 128)
// ---------------------------------------------------------------------------
__global__ __launch_bounds__(256)
void quant_rows(const float* __restrict__ src, int lds, int cols,
                int8_t* __restrict__ d1, int8_t* __restrict__ d2, int ldd,
                float* __restrict__ scale)
{
    const int row = blockIdx.x * 8 + (threadIdx.x >> 5);
    const int lane = threadIdx.x & 31;
    const float* s = src + (long)row * lds;
    const int nb = cols >> 7;          // 128-col blocks
    float vals[16];
    float mx = 0.0f;
#pragma unroll 4
    for (int b = 0; b < nb; b++) {
        float4 v = *(const float4*)(s + b * 128 + lane * 4);
        vals[b * 4 + 0] = v.x; vals[b * 4 + 1] = v.y;
        vals[b * 4 + 2] = v.z; vals[b * 4 + 3] = v.w;
        mx = fmaxf(mx, fmaxf(fmaxf(fabsf(v.x), fabsf(v.y)), fmaxf(fabsf(v.z), fabsf(v.w))));
    }
#pragma unroll
    for (int o = 16; o > 0; o >>= 1) mx = fmaxf(mx, __shfl_xor_sync(0xFFFFFFFFu, mx, o));
    if (lane == 0) scale[row] = mx * (1.0f / 127.0f);
    const float inv = (mx > 0.0f) ? 127.0f / mx : 0.0f;
#pragma unroll 4
    for (int b = 0; b < nb; b++) {
        int a1[4], a2[4];
#pragma unroll
        for (int j = 0; j < 4; j++) q2(vals[b * 4 + j], inv, a1[j], a2[j]);
        long o = (long)row * ldd + b * 128 + lane * 4;
        *(uint32_t*)(d1 + o) = pack4(a1[0], a1[1], a1[2], a1[3]);
        *(uint32_t*)(d2 + o) = pack4(a2[0], a2[1], a2[2], a2[3]);
    }
}

// ---------------------------------------------------------------------------
// transpose + quantize: src [16384, lds] column-slab (dcol0..+512) ->
// dst [512][16384] with per-(d, chunk) scale.  grid (16 dblocks, 64 chunks)
// ---------------------------------------------------------------------------
__global__ __launch_bounds__(256)
void transquant(const float* __restrict__ src, int lds, int dcol0,
                int8_t* __restrict__ d1, int8_t* __restrict__ d2,
                float* __restrict__ scale)
{
    __shared__ float sh[32][257];
    __shared__ float smax[32];
    const int z = blockIdx.y, d0 = blockIdx.x * 32;
    const int tid = threadIdx.x;
#pragma unroll
    for (int i = 0; i < 32; i++) {
        int e = tid + 256 * i;
        int t = e >> 5, d = e & 31;
        sh[d][t] = src[(long)(z * 256 + t) * lds + dcol0 + d0 + d];
    }
    __syncthreads();
    {
        int d = tid >> 3, j = tid & 7;
        float m = 0.0f;
        for (int t = j * 32; t < j * 32 + 32; t++) m = fmaxf(m, fabsf(sh[d][t]));
        m = fmaxf(m, __shfl_xor_sync(0xFFFFFFFFu, m, 1));
        m = fmaxf(m, __shfl_xor_sync(0xFFFFFFFFu, m, 2));
        m = fmaxf(m, __shfl_xor_sync(0xFFFFFFFFu, m, 4));
        if (j == 0) { smax[d] = m; scale[z * 512 + d0 + d] = m * (1.0f / 127.0f); }
    }
    __syncthreads();
#pragma unroll
    for (int i = 0; i < 8; i++) {
        int e = tid + 256 * i;
        int d = e >> 6, tq = e & 63;
        float m = smax[d];
        float inv = (m > 0.0f) ? 127.0f / m : 0.0f;
        int a1[4], a2[4];
#pragma unroll
        for (int j = 0; j < 4; j++) q2(sh[d][tq * 4 + j], inv, a1[j], a2[j]);
        long o = (long)(d0 + d) * ROWS_TOTAL + z * 256 + tq * 4;
        *(uint32_t*)(d1 + o) = pack4(a1[0], a1[1], a1[2], a1[3]);
        *(uint32_t*)(d2 + o) = pack4(a2[0], a2[1], a2[2], a2[3]);
    }
}

// ---------------------------------------------------------------------------
// exclusive prefix over chunks + quantize P rows.  grid (512 dv, 4 batch), 128 thr
// ---------------------------------------------------------------------------
__global__ __launch_bounds__(128)
void prefix_quant(const float* __restrict__ st, int8_t* __restrict__ p1,
                  int8_t* __restrict__ p2, float* __restrict__ sp)
{
    const int dv = blockIdx.x, b = blockIdx.y;
    const int tid = threadIdx.x, lane = tid & 31, wid = tid >> 5;
    __shared__ float red[4];
    __shared__ float smax;
    float acc[4] = {0.0f, 0.0f, 0.0f, 0.0f};
    for (int c = 0; c < CHUNKS_PER_BATCH; c++) {
        const int z = b * CHUNKS_PER_BATCH + c;
        float m = fmaxf(fmaxf(fabsf(acc[0]), fabsf(acc[1])), fmaxf(fabsf(acc[2]), fabsf(acc[3])));
#pragma unroll
        for (int o = 16; o > 0; o >>= 1) m = fmaxf(m, __shfl_xor_sync(0xFFFFFFFFu, m, o));
        if (lane == 0) red[wid] = m;
        __syncthreads();
        if (tid == 0) {
            float mm = fmaxf(fmaxf(red[0], red[1]), fmaxf(red[2], red[3]));
            smax = mm;
            sp[z * 512 + dv] = mm * (1.0f / 127.0f);
        }
        __syncthreads();
        float mm = smax;
        float inv = (mm > 0.0f) ? 127.0f / mm : 0.0f;
        int a1[4], a2[4];
#pragma unroll
        for (int j = 0; j < 4; j++) q2(acc[j], inv, a1[j], a2[j]);
        long o = ((long)z * 512 + dv) * 512 + tid * 4;
        *(uint32_t*)(p1 + o) = pack4(a1[0], a1[1], a1[2], a1[3]);
        *(uint32_t*)(p2 + o) = pack4(a2[0], a2[1], a2[2], a2[3]);
        float4 s = *(const float4*)(st + o);
        acc[0] += s.x; acc[1] += s.y; acc[2] += s.z; acc[3] += s.w;
        __syncthreads();
    }
}

// ---------------------------------------------------------------------------
// weight transpose + quantize: 4 weights -> rows [w*512 + n][k], per-row scale
// grid 64: z = w*16 + nblock
// ---------------------------------------------------------------------------
__global__ __launch_bounds__(256)
void wtransquant(const float* __restrict__ w0, const float* __restrict__ w1,
                 const float* __restrict__ w2, const float* __restrict__ w3,
                 int8_t* __restrict__ d1, int8_t* __restrict__ d2,
                 float* __restrict__ scale)
{
    const float* Ws[4] = {w0, w1, w2, w3};
    const int w = blockIdx.x >> 4, n0 = (blockIdx.x & 15) * 32;
    const float* W = Ws[w];
    __shared__ float pm[8][32];
    __shared__ float sm2[32];
    const int tid = threadIdx.x;
    {
        int n = tid & 31, kc = tid >> 5;
        float m = 0.0f;
        for (int k = kc * 64; k < kc * 64 + 64; k++)
            m = fmaxf(m, fabsf(W[(long)k * DIMD + n0 + n]));
        pm[kc][n] = m;
    }
    __syncthreads();
    if (tid < 32) {
        float m = 0.0f;
#pragma unroll
        for (int kc = 0; kc < 8; kc++) m = fmaxf(m, pm[kc][tid]);
        sm2[tid] = m;
        scale[w * 512 + n0 + tid] = m * (1.0f / 127.0f);
    }
    __syncthreads();
#pragma unroll
    for (int i = 0; i < 16; i++) {
        int e = tid + 256 * i;
        int n = e >> 7, kq = e & 127;
        float m = sm2[n];
        float inv = (m > 0.0f) ? 127.0f / m : 0.0f;
        int a1[4], a2[4];
#pragma unroll
        for (int j = 0; j < 4; j++) q2(W[(long)(kq * 4 + j) * DIMD + n0 + n], inv, a1[j], a2[j]);
        long o = (long)(w * 512 + n0 + n) * 512 + kq * 4;
        *(uint32_t*)(d1 + o) = pack4(a1[0], a1[1], a1[2], a1[3]);
        *(uint32_t*)(d2 + o) = pack4(a2[0], a2[1], a2[2], a2[3]);
    }
}

// ---------------------------------------------------------------------------
// launcher
// ---------------------------------------------------------------------------
extern "C" void kernel_launch(void* const* d_in, const int* in_sizes, int n_in,
                              void* d_out, int out_size)
{
    int xi = 0;
    for (int i = 0; i < n_in; i++)
        if (in_sizes[i] == (int)(ROWS_TOTAL * DIMD)) { xi = i; break; }
    const float* W[4]; int wi = 0;
    for (int i = 0; i < n_in && wi < 4; i++) { if (i == xi) continue; W[wi++] = (const float*)d_in[i]; }
    const float* x = (const float*)d_in[xi];

    int8_t *x1, *x2, *w1, *w2, *q1, *q2p, *k1, *k2, *kt1, *kt2, *vt1, *vt2;
    int8_t *p1, *p2, *s1, *s2, *y1, *y2;
    float *sx, *sw, *qkv, *sq, *sk, *skt, *svt, *st, *sp, *scf, *ss, *y, *sy;
    cudaGetSymbolAddress((void**)&x1, g_x1);   cudaGetSymbolAddress((void**)&x2, g_x2);
    cudaGetSymbolAddress((void**)&sx, g_sx);
    cudaGetSymbolAddress((void**)&w1, g_w1);   cudaGetSymbolAddress((void**)&w2, g_w2);
    cudaGetSymbolAddress((void**)&sw, g_sw);
    cudaGetSymbolAddress((void**)&qkv, g_qkv);
    cudaGetSymbolAddress((void**)&q1, g_q1);   cudaGetSymbolAddress((void**)&q2p, g_q2);
    cudaGetSymbolAddress((void**)&k1, g_k1);   cudaGetSymbolAddress((void**)&k2, g_k2);
    cudaGetSymbolAddress((void**)&sq, g_sq);   cudaGetSymbolAddress((void**)&sk, g_sk);
    cudaGetSymbolAddress((void**)&kt1, g_kt1); cudaGetSymbolAddress((void**)&kt2, g_kt2);
    cudaGetSymbolAddress((void**)&vt1, g_vt1); cudaGetSymbolAddress((void**)&vt2, g_vt2);
    cudaGetSymbolAddress((void**)&skt, g_skt); cudaGetSymbolAddress((void**)&svt, g_svt);
    cudaGetSymbolAddress((void**)&st, g_st);
    cudaGetSymbolAddress((void**)&p1, g_p1);   cudaGetSymbolAddress((void**)&p2, g_p2);
    cudaGetSymbolAddress((void**)&sp, g_sp);
    cudaGetSymbolAddress((void**)&scf, g_scf);
    cudaGetSymbolAddress((void**)&s1, g_s1);   cudaGetSymbolAddress((void**)&s2, g_s2);
    cudaGetSymbolAddress((void**)&ss, g_ss);
    cudaGetSymbolAddress((void**)&y, g_y);
    cudaGetSymbolAddress((void**)&y1, g_y1);   cudaGetSymbolAddress((void**)&y2, g_y2);
    cudaGetSymbolAddress((void**)&sy, g_sy);

    cudaFuncSetAttribute(gemm_i8<0>, cudaFuncAttributeMaxDynamicSharedMemorySize, GSMEM);
    cudaFuncSetAttribute(gemm_i8<2>, cudaFuncAttributeMaxDynamicSharedMemorySize, GSMEM);
    cudaFuncSetAttribute(gemm_i8<3>, cudaFuncAttributeMaxDynamicSharedMemorySize, GSMEM);

    const long ST = (long)DIMD * DIMD;          // 262144
    const long SS = (long)CCHUNK * CCHUNK;      // 65536
    const long CHY = (long)CCHUNK * DIMD;       // 131072

    // 1) quantize x; 2) weights
    quant_rows<<<2048, 256>>>(x, DIMD, DIMD, x1, x2, DIMD, sx);
    wtransquant<<<64, 256>>>(W[0], W[1], W[2], W[3], w1, w2, sw);

    // 3) qkv = x @ [Wq|Wk|Wv]^T  (M=16384, N=1536, K=512) -> f32
    gemm_i8<0><<<dim3(12, 128, 1), 256, GSMEM>>>(
        x1, x2, 0, DIMD, sx, 0, w1, w2, 0, DIMD, sw, 0,
        qkv, 0, 1536, nullptr, DIMD);

    // 4-7) quantize q, k (token rows); k^T, v^T (per-(d,chunk))
    quant_rows<<<2048, 256>>>(qkv,        1536, DIMD, q1, q2p, DIMD, sq);
    quant_rows<<<2048, 256>>>(qkv + 512,  1536, DIMD, k1, k2,  DIMD, sk);
    transquant<<<dim3(16, NCHUNKS), 256>>>(qkv, 1536, 512,  kt1, kt2, skt);
    transquant<<<dim3(16, NCHUNKS), 256>>>(qkv, 1536, 1024, vt1, vt2, svt);

    // 8) per-chunk state S_c = V_c^T K_c (f32): M=N=512, K=256, z=chunk
    gemm_i8<0><<<dim3(4, 4, NCHUNKS), 256, GSMEM>>>(
        vt1, vt2, 256, ROWS_TOTAL, svt, 512,
        kt1, kt2, 256, ROWS_TOTAL, skt, 512,
        st, ST, DIMD, nullptr, CCHUNK);

    // 9) exclusive prefix + quantize P
    prefix_quant<<<dim3(512, 4), 128>>>(st, p1, p2, sp);

    // 10) masked intra-chunk scores (f32): M=N=256, K=512
    gemm_i8<2><<<dim3(2, 2, NCHUNKS), 256, GSMEM>>>(
        q1, q2p, (long)CCHUNK * DIMD, DIMD, sq, CCHUNK,
        k1, k2,  (long)CCHUNK * DIMD, DIMD, sk, CCHUNK,
        scf, SS, CCHUNK, nullptr, DIMD);

    // 11) quantize scores rows (16384 rows of 256)
    quant_rows<<<2048, 256>>>(scf, CCHUNK, CCHUNK, s1, s2, CCHUNK, ss);

    // 12) y = Q_c @ P_c^T  (M=256, N=512, K=512)
    gemm_i8<0><<<dim3(4, 2, NCHUNKS), 256, GSMEM>>>(
        q1, q2p, (long)CCHUNK * DIMD, DIMD, sq, CCHUNK,
        p1, p2, ST, DIMD, sp, 512,
        y, CHY, DIMD, nullptr, DIMD);

    // 13) y += scores_c @ V_c  (M=256, N=512, K=256), aux-add in place
    gemm_i8<3><<<dim3(4, 2, NCHUNKS), 256, GSMEM>>>(
        s1, s2, SS, CCHUNK, ss, CCHUNK,
        vt1, vt2, 256, ROWS_TOTAL, svt, 512,
        y, CHY, DIMD, y, CCHUNK);

    // 14) quantize y; 15) out = y @ Wo^T (f32)
    quant_rows<<<2048, 256>>>(y, DIMD, DIMD, y1, y2, DIMD, sy);
    gemm_i8<0><<<dim3(4, 128, 1), 256, GSMEM>>>(
        y1, y2, 0, DIMD, sy, 0,
        w1 + (size_t)1536 * 512, w2 + (size_t)1536 * 512, 0, DIMD, sw + 1536, 0,
        (float*)d_out, 0, DIMD, nullptr, DIMD);
}

// round 8
// speedup vs baseline: 2.4693x; 2.4693x over previous
#include <cuda_runtime.h>
#include <cuda_bf16.h>
#include <cstdint>
#include <cstddef>

// Problem constants: B=4, S=4096, D=512
#define ROWS_TOTAL 16384
#define DIMD 512
#define CCHUNK 256
#define NCHUNKS 64
#define CHUNKS_PER_BATCH 16

#define NE  ((size_t)ROWS_TOTAL * DIMD)             // 8,388,608
#define NQKV ((size_t)ROWS_TOTAL * 3 * DIMD)        // 25,165,824
#define STN ((size_t)NCHUNKS * DIMD * DIMD)         // 16,777,216
#define SCN ((size_t)NCHUNKS * CCHUNK * CCHUNK)     // 4,194,304

typedef __nv_bfloat16 bf;

// ---------------------------------------------------------------------------
// Scratch (static device globals)
// ---------------------------------------------------------------------------
__device__ __align__(16) bf g_xh[NE], g_xl[NE];
__device__ __align__(16) bf g_qkvh[NQKV], g_qkvl[NQKV];     // [16384][1536]
__device__ __align__(16) bf g_yh[NE], g_yl[NE];
__device__ __align__(16) bf g_kth[NE], g_ktl[NE];           // [512][16384]
__device__ __align__(16) bf g_vth[NE], g_vtl[NE];
__device__ __align__(16) bf g_wth[(size_t)4 * DIMD * DIMD]; // [4][512 n][512 k] = W^T
__device__ __align__(16) bf g_wtl[(size_t)4 * DIMD * DIMD];
__device__ __align__(16) bf g_ph[STN], g_pl[STN];
__device__ __align__(16) bf g_sch[SCN], g_scl[SCN];
__device__ __align__(16) float g_st[STN];

// ---------------------------------------------------------------------------
// helpers
// ---------------------------------------------------------------------------
__device__ __forceinline__ uint32_t smem_u32(const void* p) {
    uint32_t a;
    asm("{ .reg .u64 t; cvta.to.shared.u64 t, %1; cvt.u32.u64 %0, t; }" : "=r"(a) : "l"(p));
    return a;
}
__device__ __forceinline__ void cp16(uint32_t dst, const void* src) {
    asm volatile("cp.async.cg.shared.global [%0], [%1], 16;" :: "r"(dst), "l"(src));
}
#define CP_COMMIT() asm volatile("cp.async.commit_group;" ::: "memory")
template <int N> __device__ __forceinline__ void cp_wait() {
    asm volatile("cp.async.wait_group %0;" :: "n"(N) : "memory");
}
__device__ __forceinline__ void ldm4(uint32_t* r, uint32_t addr) {
    asm volatile("ldmatrix.sync.aligned.m8n8.x4.shared.b16 {%0,%1,%2,%3}, [%4];"
                 : "=r"(r[0]), "=r"(r[1]), "=r"(r[2]), "=r"(r[3]) : "r"(addr));
}
__device__ __forceinline__ void mma16816(float* d, const uint32_t* a, uint32_t b0, uint32_t b1) {
    asm volatile("mma.sync.aligned.m16n8k16.row.col.f32.bf16.bf16.f32 "
                 "{%0,%1,%2,%3},{%4,%5,%6,%7},{%8,%9},{%0,%1,%2,%3};"
                 : "+f"(d[0]), "+f"(d[1]), "+f"(d[2]), "+f"(d[3])
                 : "r"(a[0]), "r"(a[1]), "r"(a[2]), "r"(a[3]), "r"(b0), "r"(b1));
}
__device__ __forceinline__ void split1(float v, uint16_t& h, uint16_t& l) {
    __nv_bfloat16 hb = __float2bfloat16(v);
    __nv_bfloat16 lb = __float2bfloat16(v - __bfloat162float(hb));
    h = __bfloat16_as_ushort(hb);
    l = __bfloat16_as_ushort(lb);
}
__device__ __forceinline__ void split2(float v0, float v1, uint32_t& hi, uint32_t& lo) {
    uint16_t h0, l0, h1, l1;
    split1(v0, h0, l0); split1(v1, h1, l1);
    hi = (uint32_t)h0 | ((uint32_t)h1 << 16);
    lo = (uint32_t)l0 | ((uint32_t)l1 << 16);
}

// ---------------------------------------------------------------------------
// warp-MMA GEMM, CTA tile 128(M) x 256(N), 8 warps (2x4), warp tile 64x64.
// C = sum_k A1*B1^T (+ sum_k A2*B2^T if K2>0), split-bf16 3-term, fp32 accum.
// 3-stage cp.async pipeline, one __syncthreads per k-chunk.
// MODE 0: C f32; MODE 1: split planes; MODE 2: split planes + causal mask.
// ---------------------------------------------------------------------------
#define STAGE_BYTES 49152
#define GSMEM (3 * STAGE_BYTES)   // 144 KB

template <int MODE>
__global__ __launch_bounds__(256, 1)
void gemm2(const bf* __restrict__ A1h, const bf* __restrict__ A1l, long sA1, int lda1,
           const bf* __restrict__ B1h, const bf* __restrict__ B1l, long sB1, int ldb1, int K1,
           const bf* __restrict__ A2h, const bf* __restrict__ A2l, long sA2, int lda2,
           const bf* __restrict__ B2h, const bf* __restrict__ B2l, long sB2, int ldb2, int K2,
           void* __restrict__ Chv, void* __restrict__ Clv, long sC, int ldc)
{
    extern __shared__ __align__(128) char dsm[];
    const uint32_t sm = smem_u32(dsm);

    const int tid = threadIdx.x, lane = tid & 31, wid = tid >> 5;
    const int wm = wid & 1, wn = wid >> 1;      // 2 x 4
    const long z = blockIdx.z;
    const int bm = blockIdx.y * 128, bn = blockIdx.x * 256;

    float acc[4][8][4];
#pragma unroll
    for (int i = 0; i < 4; i++)
#pragma unroll
        for (int j = 0; j < 8; j++)
#pragma unroll
            for (int q = 0; q < 4; q++) acc[i][j][q] = 0.0f;

    // SMEM per stage: A 128 rows x 128B (hi 64B | lo 64B), B 256 rows x 128B.
    // swizzle: byte = row*128 + ((chunk16 ^ (row&7)) << 4), chunks 0-3 hi, 4-7 lo
    auto load = [&](const bf* Ah, const bf* Al, int lda,
                    const bf* Bh, const bf* Bl, int ldb, int c, int buf) {
        const int k0 = c * 32;
        const uint32_t sb = sm + buf * STAGE_BYTES;
#pragma unroll
        for (int i = 0; i < 4; i++) {
            int e = tid + 256 * i;              // A: 1024 cp16
            int row = e >> 3, ch = e & 7;
            int kc = k0 + (ch & 3) * 8;
            const bf* src = (ch < 4 ? Ah : Al) + (long)row * lda + kc;
            uint32_t sw = (uint32_t)(row * 128 + ((ch ^ (row & 7)) << 4));
            cp16(sb + sw, src);
        }
#pragma unroll
        for (int i = 0; i < 8; i++) {
            int e = tid + 256 * i;              // B: 2048 cp16
            int row = e >> 3, ch = e & 7;
            int kc = k0 + (ch & 3) * 8;
            const bf* src = (ch < 4 ? Bh : Bl) + (long)row * ldb + kc;
            uint32_t sw = (uint32_t)(row * 128 + ((ch ^ (row & 7)) << 4));
            cp16(sb + 16384 + sw, src);
        }
    };

    auto compute = [&](int buf) {
        const uint32_t ba = sm + buf * STAGE_BYTES;
        const uint32_t bb = ba + 16384;
#pragma unroll
        for (int kh2 = 0; kh2 < 2; kh2++) {
            uint32_t ahf[4][4], alf[4][4];
#pragma unroll
            for (int mf = 0; mf < 4; mf++) {
                int row = wm * 64 + mf * 16 + (lane & 7) + ((lane >> 3) & 1) * 8;
                int ch = kh2 * 2 + (lane >> 4);
                ldm4(ahf[mf], ba + row * 128 + ((ch ^ (row & 7)) << 4));
                ldm4(alf[mf], ba + row * 128 + (((ch + 4) ^ (row & 7)) << 4));
            }
#pragma unroll
            for (int bi = 0; bi < 4; bi++) {
                uint32_t bhf[4], blf[4];
                int row = wn * 64 + bi * 16 + (lane & 7) + (lane >> 4) * 8;
                int ch = kh2 * 2 + ((lane >> 3) & 1);
                ldm4(bhf, bb + row * 128 + ((ch ^ (row & 7)) << 4));
                ldm4(blf, bb + row * 128 + (((ch + 4) ^ (row & 7)) << 4));
#pragma unroll
                for (int mf = 0; mf < 4; mf++) {
#pragma unroll
                    for (int half = 0; half < 2; half++) {
                        int nf = bi * 2 + half;
                        mma16816(acc[mf][nf], ahf[mf], bhf[2 * half], bhf[2 * half + 1]);
                        mma16816(acc[mf][nf], ahf[mf], blf[2 * half], blf[2 * half + 1]);
                        mma16816(acc[mf][nf], alf[mf], bhf[2 * half], bhf[2 * half + 1]);
                    }
                }
            }
        }
    };

    auto run = [&](const bf* Ahp, const bf* Alp, long sA, int lda,
                   const bf* Bhp, const bf* Blp, long sB, int ldb, int K, bool first) {
        const bf* Ah = Ahp + z * sA + (long)bm * lda;
        const bf* Al = Alp + z * sA + (long)bm * lda;
        const bf* Bh = Bhp + z * sB + (long)bn * ldb;
        const bf* Bl = Blp + z * sB + (long)bn * ldb;
        const int nch = K >> 5;
        if (!first) __syncthreads();    // protect stage buffers across runs
        load(Ah, Al, lda, Bh, Bl, ldb, 0, 0); CP_COMMIT();
        if (nch > 1) { load(Ah, Al, lda, Bh, Bl, ldb, 1, 1); CP_COMMIT(); }
        for (int c = 0; c < nch; c++) {
            if (c + 1 < nch) cp_wait<1>(); else cp_wait<0>();
            __syncthreads();
            if (c + 2 < nch) {
                load(Ah, Al, lda, Bh, Bl, ldb, c + 2, (c + 2) % 3);
                CP_COMMIT();
            }
            compute(c % 3);
        }
    };

    run(A1h, A1l, sA1, lda1, B1h, B1l, sB1, ldb1, K1, true);
    if (K2 > 0) run(A2h, A2l, sA2, lda2, B2h, B2l, sB2, ldb2, K2, false);

    // epilogue
    const long rbase = z * sC;
#pragma unroll
    for (int mf = 0; mf < 4; mf++) {
#pragma unroll
        for (int nf = 0; nf < 8; nf++) {
            float* d = acc[mf][nf];
            int r = bm + wm * 64 + mf * 16 + (lane >> 2);
            int c = bn + wn * 64 + nf * 8 + (lane & 3) * 2;
            long i0 = rbase + (long)r * ldc + c;
            long i1 = i0 + 8L * ldc;
            if (MODE == 0) {
                float* C = (float*)Chv;
                *(float2*)(C + i0) = make_float2(d[0], d[1]);
                *(float2*)(C + i1) = make_float2(d[2], d[3]);
            } else {
                float v0 = d[0], v1 = d[1], v2 = d[2], v3 = d[3];
                if (MODE == 2) {
                    if (c     > r)     v0 = 0.0f;
                    if (c + 1 > r)     v1 = 0.0f;
                    if (c     > r + 8) v2 = 0.0f;
                    if (c + 1 > r + 8) v3 = 0.0f;
                }
                uint32_t hi0, lo0, hi1, lo1;
                split2(v0, v1, hi0, lo0);
                split2(v2, v3, hi1, lo1);
                bf* Ch = (bf*)Chv; bf* Cl = (bf*)Clv;
                *(uint32_t*)(Ch + i0) = hi0;
                *(uint32_t*)(Cl + i0) = lo0;
                *(uint32_t*)(Ch + i1) = hi1;
                *(uint32_t*)(Cl + i1) = lo1;
            }
        }
    }
}

// ---------------------------------------------------------------------------
// pre/post passes
// ---------------------------------------------------------------------------
__global__ __launch_bounds__(256)
void pack_split(const float4* __restrict__ in, bf* __restrict__ hp,
                bf* __restrict__ lp, int n4)
{
    for (int i = blockIdx.x * 256 + threadIdx.x; i < n4; i += gridDim.x * 256) {
        float4 f = in[i];
        uint32_t h0, l0, h1, l1;
        split2(f.x, f.y, h0, l0);
        split2(f.z, f.w, h1, l1);
        *(uint2*)(hp + (size_t)i * 4) = make_uint2(h0, h1);
        *(uint2*)(lp + (size_t)i * 4) = make_uint2(l0, l1);
    }
}

__global__ __launch_bounds__(256)
void wtrans(const float* __restrict__ w0, const float* __restrict__ w1,
            const float* __restrict__ w2, const float* __restrict__ w3,
            bf* __restrict__ th, bf* __restrict__ tl)
{
    const float* Ws[4] = {w0, w1, w2, w3};
    const float* W = Ws[blockIdx.z];
    __shared__ float s[32][33];
    int n0 = blockIdx.x * 32, k0 = blockIdx.y * 32;
    int tx = threadIdx.x & 31, ty = threadIdx.x >> 5;
#pragma unroll
    for (int i = 0; i < 4; i++)
        s[ty + 8 * i][tx] = W[(long)(k0 + ty + 8 * i) * DIMD + n0 + tx];
    __syncthreads();
#pragma unroll
    for (int i = 0; i < 4; i++) {
        float v = s[tx][ty + 8 * i];
        uint16_t h, l;
        split1(v, h, l);
        size_t o = (size_t)blockIdx.z * DIMD * DIMD + (size_t)(n0 + ty + 8 * i) * DIMD + k0 + tx;
        ((uint16_t*)th)[o] = h;
        ((uint16_t*)tl)[o] = l;
    }
}

// dual-plane transpose: z=0 -> k columns (+DIMD), z=1 -> v columns (+2*DIMD)
__global__ __launch_bounds__(256)
void utrans2(const bf* __restrict__ inh, const bf* __restrict__ inl,
             bf* __restrict__ kth, bf* __restrict__ ktl,
             bf* __restrict__ vth, bf* __restrict__ vtl)
{
    __shared__ bf sh[32][33], sl[32][33];
    const int lds = 3 * DIMD;
    const int zc = blockIdx.z;
    const bf* ih = inh + (zc + 1) * DIMD;
    const bf* il = inl + (zc + 1) * DIMD;
    bf* oh = zc ? vth : kth;
    bf* ol = zc ? vtl : ktl;
    int c0 = blockIdx.x * 32, r0 = blockIdx.y * 32;
    int tx = threadIdx.x & 31, ty = threadIdx.x >> 5;
#pragma unroll
    for (int i = 0; i < 4; i++) {
        long src = (long)(r0 + ty + 8 * i) * lds + c0 + tx;
        sh[ty + 8 * i][tx] = ih[src];
        sl[ty + 8 * i][tx] = il[src];
    }
    __syncthreads();
#pragma unroll
    for (int i = 0; i < 4; i++) {
        long dst = (long)(c0 + ty + 8 * i) * ROWS_TOTAL + r0 + tx;
        oh[dst] = sh[tx][ty + 8 * i];
        ol[dst] = sl[tx][ty + 8 * i];
    }
}

__global__ __launch_bounds__(256)
void prefix_split(const float* __restrict__ st, bf* __restrict__ ph, bf* __restrict__ pl)
{
    const int e = blockIdx.x * 256 + threadIdx.x;
    const int b = blockIdx.y;
    float run = 0.0f;
    for (int c = 0; c < CHUNKS_PER_BATCH; c++) {
        size_t idx = ((size_t)(b * CHUNKS_PER_BATCH + c)) * ((size_t)DIMD * DIMD) + e;
        uint16_t h, l;
        split1(run, h, l);
        ((uint16_t*)ph)[idx] = h;
        ((uint16_t*)pl)[idx] = l;
        run += st[idx];
    }
}

// ---------------------------------------------------------------------------
// launcher
// ---------------------------------------------------------------------------
extern "C" void kernel_launch(void* const* d_in, const int* in_sizes, int n_in,
                              void* d_out, int out_size)
{
    int xi = 0;
    for (int i = 0; i < n_in; i++)
        if (in_sizes[i] == (int)(ROWS_TOTAL * DIMD)) { xi = i; break; }
    const float* W[4]; int wi = 0;
    for (int i = 0; i < n_in && wi < 4; i++) { if (i == xi) continue; W[wi++] = (const float*)d_in[i]; }
    const float* x = (const float*)d_in[xi];

    bf *xh, *xl, *qkvh, *qkvl, *yh, *yl, *kth, *ktl, *vth, *vtl, *wth, *wtl, *ph, *pl, *sch, *scl;
    float *st;
    cudaGetSymbolAddress((void**)&xh, g_xh);     cudaGetSymbolAddress((void**)&xl, g_xl);
    cudaGetSymbolAddress((void**)&qkvh, g_qkvh); cudaGetSymbolAddress((void**)&qkvl, g_qkvl);
    cudaGetSymbolAddress((void**)&yh, g_yh);     cudaGetSymbolAddress((void**)&yl, g_yl);
    cudaGetSymbolAddress((void**)&kth, g_kth);   cudaGetSymbolAddress((void**)&ktl, g_ktl);
    cudaGetSymbolAddress((void**)&vth, g_vth);   cudaGetSymbolAddress((void**)&vtl, g_vtl);
    cudaGetSymbolAddress((void**)&wth, g_wth);   cudaGetSymbolAddress((void**)&wtl, g_wtl);
    cudaGetSymbolAddress((void**)&ph, g_ph);     cudaGetSymbolAddress((void**)&pl, g_pl);
    cudaGetSymbolAddress((void**)&sch, g_sch);   cudaGetSymbolAddress((void**)&scl, g_scl);
    cudaGetSymbolAddress((void**)&st, g_st);

    cudaFuncSetAttribute(gemm2<0>, cudaFuncAttributeMaxDynamicSharedMemorySize, GSMEM);
    cudaFuncSetAttribute(gemm2<1>, cudaFuncAttributeMaxDynamicSharedMemorySize, GSMEM);
    cudaFuncSetAttribute(gemm2<2>, cudaFuncAttributeMaxDynamicSharedMemorySize, GSMEM);

    const long ST = (long)DIMD * DIMD;            // 262144
    const long SS = (long)CCHUNK * CCHUNK;        // 65536
    const long CHQ = (long)CCHUNK * 3 * DIMD;     // 393216 (chunk stride in qkv buffer)
    const long CHY = (long)CCHUNK * DIMD;         // 131072

    // pack x; transpose+split weights (z: 0=Wq,1=Wk,2=Wv,3=Wo)
    pack_split<<<4096, 256>>>((const float4*)x, xh, xl, (int)(NE / 4));
    wtrans<<<dim3(16, 16, 4), 256>>>(W[0], W[1], W[2], W[3], wth, wtl);

    // fused q|k|v projection: [16384,1536] = x @ [Wq|Wk|Wv]
    gemm2<1><<<dim3(6, 128, 1), 256, GSMEM>>>(
        xh, xl, 0, DIMD, wth, wtl, 0, DIMD, DIMD,
        nullptr, nullptr, 0, 0, nullptr, nullptr, 0, 0, 0,
        qkvh, qkvl, 0, 3 * DIMD);

    // k^T, v^T (both planes, both tensors in one launch)
    utrans2<<<dim3(16, 512, 2), 256>>>(qkvh, qkvl, kth, ktl, vth, vtl);

    // per-chunk state S_c = V_c^T K_c (f32), M=512, N=512, K=256
    gemm2<0><<<dim3(2, 4, NCHUNKS), 256, GSMEM>>>(
        vth, vtl, CCHUNK, ROWS_TOTAL, kth, ktl, CCHUNK, ROWS_TOTAL, CCHUNK,
        nullptr, nullptr, 0, 0, nullptr, nullptr, 0, 0, 0,
        st, nullptr, ST, DIMD);

    // exclusive prefix over chunks -> P planes
    prefix_split<<<dim3((unsigned)(ST / 256), 4), 256>>>(st, ph, pl);

    // intra-chunk masked scores: M=256, N=256, K=512
    gemm2<2><<<dim3(1, 2, NCHUNKS), 256, GSMEM>>>(
        qkvh, qkvl, CHQ, 3 * DIMD, qkvh + DIMD, qkvl + DIMD, CHQ, 3 * DIMD, DIMD,
        nullptr, nullptr, 0, 0, nullptr, nullptr, 0, 0, 0,
        sch, scl, SS, CCHUNK);

    // fused Y_c = Q_c @ P_c^T + scores_c @ V_c  -> split planes
    gemm2<1><<<dim3(2, 2, NCHUNKS), 256, GSMEM>>>(
        qkvh, qkvl, CHQ, 3 * DIMD, ph, pl, ST, DIMD, DIMD,
        sch, scl, SS, CCHUNK, vth, vtl, CCHUNK, ROWS_TOTAL, CCHUNK,
        yh, yl, CHY, DIMD);

    // out = Y @ Wo (f32)
    gemm2<0><<<dim3(2, 128, 1), 256, GSMEM>>>(
        yh, yl, 0, DIMD, wth + 3 * ST, wtl + 3 * ST, 0, DIMD, DIMD,
        nullptr, nullptr, 0, 0, nullptr, nullptr, 0, 0, 0,
        d_out, nullptr, 0, DIMD);
}

// round 9
// speedup vs baseline: 2.6824x; 1.0863x over previous
#include <cuda_runtime.h>
#include <cuda_bf16.h>
#include <cstdint>
#include <cstddef>

// Problem constants: B=4, S=4096, D=512
#define ROWS_TOTAL 16384
#define DIMD 512
#define CCHUNK 256
#define NCHUNKS 64
#define CHUNKS_PER_BATCH 16

#define NE  ((size_t)ROWS_TOTAL * DIMD)             // 8,388,608
#define NQKV ((size_t)ROWS_TOTAL * 3 * DIMD)        // 25,165,824
#define STN ((size_t)NCHUNKS * DIMD * DIMD)         // 16,777,216
#define SCN ((size_t)NCHUNKS * CCHUNK * CCHUNK)     // 4,194,304

typedef __nv_bfloat16 bf;

// ---------------------------------------------------------------------------
// Scratch (static device globals)
// ---------------------------------------------------------------------------
__device__ __align__(16) bf g_xh[NE], g_xl[NE];
__device__ __align__(16) bf g_qkvh[NQKV], g_qkvl[NQKV];     // [16384][1536]
__device__ __align__(16) bf g_yh[NE], g_yl[NE];
__device__ __align__(16) bf g_kth[NE], g_ktl[NE];           // [512][16384]
__device__ __align__(16) bf g_vth[NE], g_vtl[NE];
__device__ __align__(16) bf g_wth[(size_t)4 * DIMD * DIMD]; // [4][512 n][512 k] = W^T
__device__ __align__(16) bf g_wtl[(size_t)4 * DIMD * DIMD];
__device__ __align__(16) bf g_ph[STN], g_pl[STN];
__device__ __align__(16) bf g_sch[SCN], g_scl[SCN];
__device__ __align__(16) float g_st[STN];

// ---------------------------------------------------------------------------
// helpers
// ---------------------------------------------------------------------------
__device__ __forceinline__ uint32_t smem_u32(const void* p) {
    uint32_t a;
    asm("{ .reg .u64 t; cvta.to.shared.u64 t, %1; cvt.u32.u64 %0, t; }" : "=r"(a) : "l"(p));
    return a;
}
__device__ __forceinline__ void cp16(uint32_t dst, const void* src) {
    asm volatile("cp.async.cg.shared.global [%0], [%1], 16;" :: "r"(dst), "l"(src));
}
#define CP_COMMIT() asm volatile("cp.async.commit_group;" ::: "memory")
template <int N> __device__ __forceinline__ void cp_wait() {
    asm volatile("cp.async.wait_group %0;" :: "n"(N) : "memory");
}
__device__ __forceinline__ void ldm4(uint32_t* r, uint32_t addr) {
    asm volatile("ldmatrix.sync.aligned.m8n8.x4.shared.b16 {%0,%1,%2,%3}, [%4];"
                 : "=r"(r[0]), "=r"(r[1]), "=r"(r[2]), "=r"(r[3]) : "r"(addr));
}
__device__ __forceinline__ void mma16816(float* d, const uint32_t* a, uint32_t b0, uint32_t b1) {
    asm volatile("mma.sync.aligned.m16n8k16.row.col.f32.bf16.bf16.f32 "
                 "{%0,%1,%2,%3},{%4,%5,%6,%7},{%8,%9},{%0,%1,%2,%3};"
                 : "+f"(d[0]), "+f"(d[1]), "+f"(d[2]), "+f"(d[3])
                 : "r"(a[0]), "r"(a[1]), "r"(a[2]), "r"(a[3]), "r"(b0), "r"(b1));
}
__device__ __forceinline__ void split1(float v, uint16_t& h, uint16_t& l) {
    __nv_bfloat16 hb = __float2bfloat16(v);
    __nv_bfloat16 lb = __float2bfloat16(v - __bfloat162float(hb));
    h = __bfloat16_as_ushort(hb);
    l = __bfloat16_as_ushort(lb);
}
__device__ __forceinline__ void split2(float v0, float v1, uint32_t& hi, uint32_t& lo) {
    uint16_t h0, l0, h1, l1;
    split1(v0, h0, l0); split1(v1, h1, l1);
    hi = (uint32_t)h0 | ((uint32_t)h1 << 16);
    lo = (uint32_t)l0 | ((uint32_t)l1 << 16);
}

// ---------------------------------------------------------------------------
// warp-MMA GEMM, CTA tile 128(M) x 128(N), 8 warps (2m x 4n), warp tile 64x32.
// C = sum_k A1*B1^T (+ sum_k A2*B2^T if K2>0), split-bf16 3-term, fp32 accum.
// 3-stage cp.async pipeline, one __syncthreads per 32-k chunk, 2 CTAs/SM.
// MODE 0: C f32; MODE 1: split planes; MODE 2: split planes + causal mask.
// ---------------------------------------------------------------------------
#define STAGE_BYTES 32768
#define GSMEM (3 * STAGE_BYTES)   // 96 KB -> 2 CTAs/SM

template <int MODE>
__global__ __launch_bounds__(256, 2)
void gemm2(const bf* __restrict__ A1h, const bf* __restrict__ A1l, long sA1, int lda1,
           const bf* __restrict__ B1h, const bf* __restrict__ B1l, long sB1, int ldb1, int K1,
           const bf* __restrict__ A2h, const bf* __restrict__ A2l, long sA2, int lda2,
           const bf* __restrict__ B2h, const bf* __restrict__ B2l, long sB2, int ldb2, int K2,
           void* __restrict__ Chv, void* __restrict__ Clv, long sC, int ldc)
{
    extern __shared__ __align__(128) char dsm[];
    const uint32_t sm = smem_u32(dsm);

    const int tid = threadIdx.x, lane = tid & 31, wid = tid >> 5;
    const int wm = wid & 1, wn = wid >> 1;      // 2 x 4
    const long z = blockIdx.z;
    const int bm = blockIdx.y * 128, bn = blockIdx.x * 128;

    float acc[4][4][4];
#pragma unroll
    for (int i = 0; i < 4; i++)
#pragma unroll
        for (int j = 0; j < 4; j++)
#pragma unroll
            for (int q = 0; q < 4; q++) acc[i][j][q] = 0.0f;

    // SMEM per stage: A 128 rows x 128B (hi 64B | lo 64B) = 16KB, B same at +16KB.
    // swizzle: byte = row*128 + ((chunk16 ^ (row&7)) << 4), chunks 0-3 hi, 4-7 lo
    auto load = [&](const bf* Ah, const bf* Al, int lda,
                    const bf* Bh, const bf* Bl, int ldb, int c, int buf) {
        const int k0 = c * 32;
        const uint32_t sb = sm + buf * STAGE_BYTES;
#pragma unroll
        for (int i = 0; i < 4; i++) {
            int e = tid + 256 * i;              // A: 1024 cp16
            int row = e >> 3, ch = e & 7;
            int kc = k0 + (ch & 3) * 8;
            const bf* src = (ch < 4 ? Ah : Al) + (long)row * lda + kc;
            uint32_t sw = (uint32_t)(row * 128 + ((ch ^ (row & 7)) << 4));
            cp16(sb + sw, src);
        }
#pragma unroll
        for (int i = 0; i < 4; i++) {
            int e = tid + 256 * i;              // B: 1024 cp16
            int row = e >> 3, ch = e & 7;
            int kc = k0 + (ch & 3) * 8;
            const bf* src = (ch < 4 ? Bh : Bl) + (long)row * ldb + kc;
            uint32_t sw = (uint32_t)(row * 128 + ((ch ^ (row & 7)) << 4));
            cp16(sb + 16384 + sw, src);
        }
    };

    auto compute = [&](int buf) {
        const uint32_t ba = sm + buf * STAGE_BYTES;
        const uint32_t bb = ba + 16384;
#pragma unroll
        for (int kh2 = 0; kh2 < 2; kh2++) {
            uint32_t ahf[4][4], alf[4][4];
#pragma unroll
            for (int mf = 0; mf < 4; mf++) {
                int row = wm * 64 + mf * 16 + (lane & 7) + ((lane >> 3) & 1) * 8;
                int ch = kh2 * 2 + (lane >> 4);
                ldm4(ahf[mf], ba + row * 128 + ((ch ^ (row & 7)) << 4));
                ldm4(alf[mf], ba + row * 128 + (((ch + 4) ^ (row & 7)) << 4));
            }
#pragma unroll
            for (int bi = 0; bi < 2; bi++) {
                uint32_t bhf[4], blf[4];
                int row = wn * 32 + bi * 16 + (lane & 7) + (lane >> 4) * 8;
                int ch = kh2 * 2 + ((lane >> 3) & 1);
                ldm4(bhf, bb + row * 128 + ((ch ^ (row & 7)) << 4));
                ldm4(blf, bb + row * 128 + (((ch + 4) ^ (row & 7)) << 4));
#pragma unroll
                for (int mf = 0; mf < 4; mf++) {
#pragma unroll
                    for (int half = 0; half < 2; half++) {
                        int nf = bi * 2 + half;
                        mma16816(acc[mf][nf], ahf[mf], bhf[2 * half], bhf[2 * half + 1]);
                        mma16816(acc[mf][nf], ahf[mf], blf[2 * half], blf[2 * half + 1]);
                        mma16816(acc[mf][nf], alf[mf], bhf[2 * half], bhf[2 * half + 1]);
                    }
                }
            }
        }
    };

    auto run = [&](const bf* Ahp, const bf* Alp, long sA, int lda,
                   const bf* Bhp, const bf* Blp, long sB, int ldb, int K, bool first) {
        const bf* Ah = Ahp + z * sA + (long)bm * lda;
        const bf* Al = Alp + z * sA + (long)bm * lda;
        const bf* Bh = Bhp + z * sB + (long)bn * ldb;
        const bf* Bl = Blp + z * sB + (long)bn * ldb;
        const int nch = K >> 5;
        if (!first) __syncthreads();    // protect stage buffers across runs
        load(Ah, Al, lda, Bh, Bl, ldb, 0, 0); CP_COMMIT();
        if (nch > 1) { load(Ah, Al, lda, Bh, Bl, ldb, 1, 1); CP_COMMIT(); }
        for (int c = 0; c < nch; c++) {
            if (c + 1 < nch) cp_wait<1>(); else cp_wait<0>();
            __syncthreads();
            if (c + 2 < nch) {
                load(Ah, Al, lda, Bh, Bl, ldb, c + 2, (c + 2) % 3);
                CP_COMMIT();
            }
            compute(c % 3);
        }
    };

    run(A1h, A1l, sA1, lda1, B1h, B1l, sB1, ldb1, K1, true);
    if (K2 > 0) run(A2h, A2l, sA2, lda2, B2h, B2l, sB2, ldb2, K2, false);

    // epilogue
    const long rbase = z * sC;
#pragma unroll
    for (int mf = 0; mf < 4; mf++) {
#pragma unroll
        for (int nf = 0; nf < 4; nf++) {
            float* d = acc[mf][nf];
            int r = bm + wm * 64 + mf * 16 + (lane >> 2);
            int c = bn + wn * 32 + nf * 8 + (lane & 3) * 2;
            long i0 = rbase + (long)r * ldc + c;
            long i1 = i0 + 8L * ldc;
            if (MODE == 0) {
                float* C = (float*)Chv;
                *(float2*)(C + i0) = make_float2(d[0], d[1]);
                *(float2*)(C + i1) = make_float2(d[2], d[3]);
            } else {
                float v0 = d[0], v1 = d[1], v2 = d[2], v3 = d[3];
                if (MODE == 2) {
                    if (c     > r)     v0 = 0.0f;
                    if (c + 1 > r)     v1 = 0.0f;
                    if (c     > r + 8) v2 = 0.0f;
                    if (c + 1 > r + 8) v3 = 0.0f;
                }
                uint32_t hi0, lo0, hi1, lo1;
                split2(v0, v1, hi0, lo0);
                split2(v2, v3, hi1, lo1);
                bf* Ch = (bf*)Chv; bf* Cl = (bf*)Clv;
                *(uint32_t*)(Ch + i0) = hi0;
                *(uint32_t*)(Cl + i0) = lo0;
                *(uint32_t*)(Ch + i1) = hi1;
                *(uint32_t*)(Cl + i1) = lo1;
            }
        }
    }
}

// ---------------------------------------------------------------------------
// pre/post passes
// ---------------------------------------------------------------------------
__global__ __launch_bounds__(256)
void pack_split(const float4* __restrict__ in, bf* __restrict__ hp,
                bf* __restrict__ lp, int n4)
{
    for (int i = blockIdx.x * 256 + threadIdx.x; i < n4; i += gridDim.x * 256) {
        float4 f = in[i];
        uint32_t h0, l0, h1, l1;
        split2(f.x, f.y, h0, l0);
        split2(f.z, f.w, h1, l1);
        *(uint2*)(hp + (size_t)i * 4) = make_uint2(h0, h1);
        *(uint2*)(lp + (size_t)i * 4) = make_uint2(l0, l1);
    }
}

__global__ __launch_bounds__(256)
void wtrans(const float* __restrict__ w0, const float* __restrict__ w1,
            const float* __restrict__ w2, const float* __restrict__ w3,
            bf* __restrict__ th, bf* __restrict__ tl)
{
    const float* Ws[4] = {w0, w1, w2, w3};
    const float* W = Ws[blockIdx.z];
    __shared__ float s[32][33];
    int n0 = blockIdx.x * 32, k0 = blockIdx.y * 32;
    int tx = threadIdx.x & 31, ty = threadIdx.x >> 5;
#pragma unroll
    for (int i = 0; i < 4; i++)
        s[ty + 8 * i][tx] = W[(long)(k0 + ty + 8 * i) * DIMD + n0 + tx];
    __syncthreads();
#pragma unroll
    for (int i = 0; i < 4; i++) {
        float v = s[tx][ty + 8 * i];
        uint16_t h, l;
        split1(v, h, l);
        size_t o = (size_t)blockIdx.z * DIMD * DIMD + (size_t)(n0 + ty + 8 * i) * DIMD + k0 + tx;
        ((uint16_t*)th)[o] = h;
        ((uint16_t*)tl)[o] = l;
    }
}

// dual-plane transpose: z=0 -> k columns (+DIMD), z=1 -> v columns (+2*DIMD)
__global__ __launch_bounds__(256)
void utrans2(const bf* __restrict__ inh, const bf* __restrict__ inl,
             bf* __restrict__ kth, bf* __restrict__ ktl,
             bf* __restrict__ vth, bf* __restrict__ vtl)
{
    __shared__ bf sh[32][33], sl[32][33];
    const int lds = 3 * DIMD;
    const int zc = blockIdx.z;
    const bf* ih = inh + (zc + 1) * DIMD;
    const bf* il = inl + (zc + 1) * DIMD;
    bf* oh = zc ? vth : kth;
    bf* ol = zc ? vtl : ktl;
    int c0 = blockIdx.x * 32, r0 = blockIdx.y * 32;
    int tx = threadIdx.x & 31, ty = threadIdx.x >> 5;
#pragma unroll
    for (int i = 0; i < 4; i++) {
        long src = (long)(r0 + ty + 8 * i) * lds + c0 + tx;
        sh[ty + 8 * i][tx] = ih[src];
        sl[ty + 8 * i][tx] = il[src];
    }
    __syncthreads();
#pragma unroll
    for (int i = 0; i < 4; i++) {
        long dst = (long)(c0 + ty + 8 * i) * ROWS_TOTAL + r0 + tx;
        oh[dst] = sh[tx][ty + 8 * i];
        ol[dst] = sl[tx][ty + 8 * i];
    }
}

__global__ __launch_bounds__(256)
void prefix_split(const float* __restrict__ st, bf* __restrict__ ph, bf* __restrict__ pl)
{
    const int e = blockIdx.x * 256 + threadIdx.x;
    const int b = blockIdx.y;
    float run = 0.0f;
    for (int c = 0; c < CHUNKS_PER_BATCH; c++) {
        size_t idx = ((size_t)(b * CHUNKS_PER_BATCH + c)) * ((size_t)DIMD * DIMD) + e;
        uint16_t h, l;
        split1(run, h, l);
        ((uint16_t*)ph)[idx] = h;
        ((uint16_t*)pl)[idx] = l;
        run += st[idx];
    }
}

// ---------------------------------------------------------------------------
// launcher
// ---------------------------------------------------------------------------
extern "C" void kernel_launch(void* const* d_in, const int* in_sizes, int n_in,
                              void* d_out, int out_size)
{
    int xi = 0;
    for (int i = 0; i < n_in; i++)
        if (in_sizes[i] == (int)(ROWS_TOTAL * DIMD)) { xi = i; break; }
    const float* W[4]; int wi = 0;
    for (int i = 0; i < n_in && wi < 4; i++) { if (i == xi) continue; W[wi++] = (const float*)d_in[i]; }
    const float* x = (const float*)d_in[xi];

    bf *xh, *xl, *qkvh, *qkvl, *yh, *yl, *kth, *ktl, *vth, *vtl, *wth, *wtl, *ph, *pl, *sch, *scl;
    float *st;
    cudaGetSymbolAddress((void**)&xh, g_xh);     cudaGetSymbolAddress((void**)&xl, g_xl);
    cudaGetSymbolAddress((void**)&qkvh, g_qkvh); cudaGetSymbolAddress((void**)&qkvl, g_qkvl);
    cudaGetSymbolAddress((void**)&yh, g_yh);     cudaGetSymbolAddress((void**)&yl, g_yl);
    cudaGetSymbolAddress((void**)&kth, g_kth);   cudaGetSymbolAddress((void**)&ktl, g_ktl);
    cudaGetSymbolAddress((void**)&vth, g_vth);   cudaGetSymbolAddress((void**)&vtl, g_vtl);
    cudaGetSymbolAddress((void**)&wth, g_wth);   cudaGetSymbolAddress((void**)&wtl, g_wtl);
    cudaGetSymbolAddress((void**)&ph, g_ph);     cudaGetSymbolAddress((void**)&pl, g_pl);
    cudaGetSymbolAddress((void**)&sch, g_sch);   cudaGetSymbolAddress((void**)&scl, g_scl);
    cudaGetSymbolAddress((void**)&st, g_st);

    cudaFuncSetAttribute(gemm2<0>, cudaFuncAttributeMaxDynamicSharedMemorySize, GSMEM);
    cudaFuncSetAttribute(gemm2<1>, cudaFuncAttributeMaxDynamicSharedMemorySize, GSMEM);
    cudaFuncSetAttribute(gemm2<2>, cudaFuncAttributeMaxDynamicSharedMemorySize, GSMEM);

    const long ST = (long)DIMD * DIMD;            // 262144
    const long SS = (long)CCHUNK * CCHUNK;        // 65536
    const long CHQ = (long)CCHUNK * 3 * DIMD;     // 393216 (chunk stride in qkv buffer)
    const long CHY = (long)CCHUNK * DIMD;         // 131072

    // pack x; transpose+split weights (z: 0=Wq,1=Wk,2=Wv,3=Wo)
    pack_split<<<4096, 256>>>((const float4*)x, xh, xl, (int)(NE / 4));
    wtrans<<<dim3(16, 16, 4), 256>>>(W[0], W[1], W[2], W[3], wth, wtl);

    // fused q|k|v projection: [16384,1536] = x @ [Wq|Wk|Wv]
    gemm2<1><<<dim3(12, 128, 1), 256, GSMEM>>>(
        xh, xl, 0, DIMD, wth, wtl, 0, DIMD, DIMD,
        nullptr, nullptr, 0, 0, nullptr, nullptr, 0, 0, 0,
        qkvh, qkvl, 0, 3 * DIMD);

    // k^T, v^T (both planes, both tensors in one launch)
    utrans2<<<dim3(16, 512, 2), 256>>>(qkvh, qkvl, kth, ktl, vth, vtl);

    // per-chunk state S_c = V_c^T K_c (f32), M=512, N=512, K=256
    gemm2<0><<<dim3(4, 4, NCHUNKS), 256, GSMEM>>>(
        vth, vtl, CCHUNK, ROWS_TOTAL, kth, ktl, CCHUNK, ROWS_TOTAL, CCHUNK,
        nullptr, nullptr, 0, 0, nullptr, nullptr, 0, 0, 0,
        st, nullptr, ST, DIMD);

    // exclusive prefix over chunks -> P planes
    prefix_split<<<dim3((unsigned)(ST / 256), 4), 256>>>(st, ph, pl);

    // intra-chunk masked scores: M=256, N=256, K=512
    gemm2<2><<<dim3(2, 2, NCHUNKS), 256, GSMEM>>>(
        qkvh, qkvl, CHQ, 3 * DIMD, qkvh + DIMD, qkvl + DIMD, CHQ, 3 * DIMD, DIMD,
        nullptr, nullptr, 0, 0, nullptr, nullptr, 0, 0, 0,
        sch, scl, SS, CCHUNK);

    // fused Y_c = Q_c @ P_c^T + scores_c @ V_c  -> split planes
    gemm2<1><<<dim3(4, 2, NCHUNKS), 256, GSMEM>>>(
        qkvh, qkvl, CHQ, 3 * DIMD, ph, pl, ST, DIMD, DIMD,
        sch, scl, SS, CCHUNK, vth, vtl, CCHUNK, ROWS_TOTAL, CCHUNK,
        yh, yl, CHY, DIMD);

    // out = Y @ Wo (f32)
    gemm2<0><<<dim3(4, 128, 1), 256, GSMEM>>>(
        yh, yl, 0, DIMD, wth + 3 * ST, wtl + 3 * ST, 0, DIMD, DIMD,
        nullptr, nullptr, 0, 0, nullptr, nullptr, 0, 0, 0,
        d_out, nullptr, 0, DIMD);
}